// round 11
// baseline (speedup 1.0000x reference)
#include <cuda_runtime.h>
#include <math.h>
#include <stdint.h>

#define TT 512
#define CC 128
#define HH 512
#define ROWS 1024

// ---------------- global scratch ----------------
__device__ __align__(16) float2 g_hshl [ROWS*CC];
__device__ float  g_r [ROWS*CC];
__device__ float  g_k [ROWS*CC];
__device__ float  g_v [ROWS*CC];
__device__ __align__(16) float2 g_wkhl [ROWS*CC];
__device__ float  g_y [ROWS*CC];
__device__ __align__(16) float2 g_h2hl [ROWS*CC];
__device__ __align__(16) float2 g_midhl[ROWS*HH];
// weights split hi/lo: [Wr | Wk | Wv | Wo | W1 | W2] (layout [K][N] each)
#define OFF_WR 0
#define OFF_WK 16384
#define OFF_WV 32768
#define OFF_WO 49152
#define OFF_W1 65536
#define OFF_W2 131072
__device__ __align__(16) float2 g_Whl[196608];

// ---------------- helpers ----------------
__device__ __forceinline__ float wsum(float x) {
    #pragma unroll
    for (int o = 16; o; o >>= 1) x += __shfl_xor_sync(0xffffffffu, x, o);
    return x;
}
__device__ __forceinline__ float rcpa(float x) {
    float r; asm("rcp.approx.f32 %0, %1;" : "=f"(r) : "f"(x)); return r;
}
typedef unsigned long long ull;
__device__ __forceinline__ ull pack2(float x, float y) {
    ull r; asm("mov.b64 %0, {%1, %2};" : "=l"(r) : "f"(x), "f"(y)); return r;
}
__device__ __forceinline__ void unpack2(ull p, float& x, float& y) {
    asm("mov.b64 {%0, %1}, %2;" : "=f"(x), "=f"(y) : "l"(p));
}
__device__ __forceinline__ ull fma2(ull a, ull b, ull c) {
    ull d; asm("fma.rn.f32x2 %0, %1, %2, %3;" : "=l"(d) : "l"(a), "l"(b), "l"(c)); return d;
}
__device__ __forceinline__ ull mul2(ull a, ull b) {
    ull d; asm("mul.rn.f32x2 %0, %1, %2;" : "=l"(d) : "l"(a), "l"(b)); return d;
}
__device__ __forceinline__ ull add2(ull a, ull b) {
    ull d; asm("add.rn.f32x2 %0, %1, %2;" : "=l"(d) : "l"(a), "l"(b)); return d;
}
__device__ __forceinline__ void cpasync16(uint32_t saddr, const void* g) {
    asm volatile("cp.async.ca.shared.global [%0], [%1], 16;" :: "r"(saddr), "l"(g));
}
__device__ __forceinline__ void cpcommit() { asm volatile("cp.async.commit_group;"); }
template<int N> __device__ __forceinline__ void cpwait() {
    asm volatile("cp.async.wait_group %0;" :: "n"(N));
}
__device__ __forceinline__ uint32_t s2u(const void* p) {
    return (uint32_t)__cvta_generic_to_shared(p);
}
// split x into (hi, lo) tf32 parts (3xTF32 scheme)
__device__ __forceinline__ float2 split2(float x) {
    uint32_t h; asm("cvt.rna.tf32.f32 %0, %1;" : "=r"(h) : "f"(x));
    float hf = __uint_as_float(h);
    float r = x - hf;
    uint32_t l; asm("cvt.rna.tf32.f32 %0, %1;" : "=r"(l) : "f"(r));
    return make_float2(hf, __uint_as_float(l));
}
__device__ __forceinline__ uint32_t fu(float x) { return __float_as_uint(x); }

__device__ __forceinline__ void mma_tf32(float (&c)[4], uint32_t a0, uint32_t a1,
                                         uint32_t a2, uint32_t a3,
                                         uint32_t b0, uint32_t b1) {
    asm volatile(
        "mma.sync.aligned.m16n8k8.row.col.f32.tf32.tf32.f32 "
        "{%0,%1,%2,%3}, {%4,%5,%6,%7}, {%8,%9}, {%0,%1,%2,%3};"
        : "+f"(c[0]), "+f"(c[1]), "+f"(c[2]), "+f"(c[3])
        : "r"(a0), "r"(a1), "r"(a2), "r"(a3), "r"(b0), "r"(b1));
}

// ---------------- prep: split all weights into (hi,lo) ----------------
__global__ void __launch_bounds__(256)
prep_kernel(const float* __restrict__ Wr, const float* __restrict__ Wk,
            const float* __restrict__ Wv, const float* __restrict__ Wo,
            const float* __restrict__ W1, const float* __restrict__ W2) {
    for (int i = blockIdx.x*256 + threadIdx.x; i < 196608; i += gridDim.x*256) {
        float x;
        if (i < 65536) {
            int m = i >> 14, off = i & 16383;
            const float* s = (m == 0) ? Wr : (m == 1) ? Wk : (m == 2) ? Wv : Wo;
            x = s[off];
        } else if (i < 131072) {
            x = W1[i - 65536];
        } else {
            x = W2[i - 131072];
        }
        g_Whl[i] = split2(x);
    }
}

// ---------------- fused LN1 + TemporalShift -> hs (hi,lo) ----------------
__global__ void __launch_bounds__(256)
ln_shift_kernel(const float* __restrict__ x,
                const float* __restrict__ gam, const float* __restrict__ bet,
                const float* __restrict__ mu) {
    __shared__ float sh[10][CC];
    const int tid = threadIdx.x;
    const int w = tid >> 5, lane = tid & 31;
    const int b  = blockIdx.x >> 6;
    const int t0 = (blockIdx.x & 63) << 3;

    float4 g4 = *(const float4*)(gam + (lane << 2));
    float4 b4 = *(const float4*)(bet + (lane << 2));

    for (int hr = w; hr < 10; hr += 8) {
        int t = t0 - 1 + hr;
        bool ok = (t >= 0) && (t < TT);
        float4 xv = make_float4(0.f, 0.f, 0.f, 0.f);
        if (ok) xv = *(const float4*)(x + (size_t)((b << 9) + t)*CC + (lane << 2));
        float mean = wsum((xv.x + xv.y) + (xv.z + xv.w)) * (1.0f/CC);
        float d0 = xv.x - mean, d1 = xv.y - mean, d2 = xv.z - mean, d3 = xv.w - mean;
        float rs = rsqrtf(wsum((d0*d0 + d1*d1) + (d2*d2 + d3*d3)) * (1.0f/CC) + 1e-5f);
        int c = lane << 2;
        sh[hr][c+0] = ok ? d0*rs*g4.x + b4.x : 0.f;
        sh[hr][c+1] = ok ? d1*rs*g4.y + b4.y : 0.f;
        sh[hr][c+2] = ok ? d2*rs*g4.z + b4.z : 0.f;
        sh[hr][c+3] = ok ? d3*rs*g4.w + b4.w : 0.f;
    }
    __syncthreads();
    for (int i = tid; i < 8*CC; i += 256) {
        int rl = i >> 7, c = i & (CC-1);
        float val = sh[rl+1][c];
        float shv = (c < CC/2) ? sh[rl][c] : sh[rl+2][c];
        float hsv = val + mu[c]*shv;
        g_hshl[(size_t)((b << 9) + t0 + rl)*CC + c] = split2(hsv);
    }
}

// ================= tensor-core GEMM: tile 32x64, 128 thr, 3xTF32 =================
// A: [1024][lda] float2(hi,lo); W: [K][ldw] float2(hi,lo).
// Warp w: rows wm=(w>>1)*16 .. +16, cols wn=(w&1)*32 .. +32 -> 4 m16n8 frags.
struct __align__(16) SmemM {
    float2 A[2][32][20];   // [buf][tile row][k in chunk]  (pitch 20 -> conflict-free)
    float2 W[2][16][68];   // [buf][k in chunk][n in tile] (pitch 68 -> conflict-free)
};

template<int K>
__device__ __forceinline__ void gemm_mma(SmemM& S,
                                         const float2* __restrict__ Ahl, int lda, int bm,
                                         const float2* __restrict__ Whl, int ldw, int bn,
                                         float (&c)[4][4]) {
    const int tid = threadIdx.x, w = tid >> 5, lane = tid & 31;
    const int g = lane >> 2, t = lane & 3;
    const int wm = (w >> 1) << 4, wn = (w & 1) << 5;
    constexpr int NC = K / 16;

    auto stage = [&](int ck, int buf) {
        #pragma unroll
        for (int j = 0; j < 2; j++) {                 // A chunk: 32 rows x 16 f2
            int idx = tid + j*128;                    // 0..255 float4s
            int row = idx >> 3, q = idx & 7;
            cpasync16(s2u(&S.A[buf][row][q*2]),
                      Ahl + (size_t)(bm + row)*lda + ck*16 + q*2);
        }
        #pragma unroll
        for (int j = 0; j < 4; j++) {                 // W chunk: 16 k x 64 f2
            int idx = tid + j*128;                    // 0..511 float4s
            int kr = idx >> 5, q = idx & 31;
            cpasync16(s2u(&S.W[buf][kr][q*2]),
                      Whl + (size_t)(ck*16 + kr)*ldw + bn + q*2);
        }
        cpcommit();
    };

    stage(0, 0);
    #pragma unroll
    for (int nf = 0; nf < 4; nf++)
        #pragma unroll
        for (int i = 0; i < 4; i++) c[nf][i] = 0.f;

    #pragma unroll 1
    for (int ck = 0; ck < NC; ck++) {
        if (ck + 1 < NC) { stage(ck + 1, (ck + 1) & 1); cpwait<1>(); }
        else             { cpwait<0>(); }
        __syncthreads();
        const int buf = ck & 1;
        #pragma unroll
        for (int k8 = 0; k8 < 2; k8++) {
            const int kb = k8 << 3;
            float2 a00 = S.A[buf][wm + g    ][kb + t];
            float2 a10 = S.A[buf][wm + g + 8][kb + t];
            float2 a01 = S.A[buf][wm + g    ][kb + t + 4];
            float2 a11 = S.A[buf][wm + g + 8][kb + t + 4];
            uint32_t ah0 = fu(a00.x), ah1 = fu(a10.x), ah2 = fu(a01.x), ah3 = fu(a11.x);
            uint32_t al0 = fu(a00.y), al1 = fu(a10.y), al2 = fu(a01.y), al3 = fu(a11.y);
            #pragma unroll
            for (int nf = 0; nf < 4; nf++) {
                float2 b0 = S.W[buf][kb + t    ][wn + (nf << 3) + g];
                float2 b1 = S.W[buf][kb + t + 4][wn + (nf << 3) + g];
                mma_tf32(c[nf], ah0, ah1, ah2, ah3, fu(b0.x), fu(b1.x));  // hi*hi
                mma_tf32(c[nf], ah0, ah1, ah2, ah3, fu(b0.y), fu(b1.y));  // hi*lo
                mma_tf32(c[nf], al0, al1, al2, al3, fu(b0.x), fu(b1.x));  // lo*hi
            }
        }
        __syncthreads();
    }
}

// ---------------- r/k/v GEMMs: grid (2, 32, 3), 128 thr ----------------
__global__ void __launch_bounds__(128)
rkv_kernel(const float* __restrict__ br, const float* __restrict__ bk,
           const float* __restrict__ bv) {
    __shared__ SmemM S;
    const int z = blockIdx.z;
    const float2* Wz = g_Whl + ((z == 0) ? OFF_WR : (z == 1) ? OFF_WK : OFF_WV);
    const float* bb  = (z == 0) ? br : (z == 1) ? bk : bv;
    float* o         = (z == 0) ? g_r : (z == 1) ? g_k : g_v;
    const int bn = blockIdx.x << 6, bm = blockIdx.y << 5;
    float c[4][4];
    gemm_mma<CC>(S, g_hshl, CC, bm, Wz, CC, bn, c);
    const int lane = threadIdx.x & 31, w = threadIdx.x >> 5;
    const int g = lane >> 2, t = lane & 3;
    const int wm = (w >> 1) << 4, wn = (w & 1) << 5;
    #pragma unroll
    for (int nf = 0; nf < 4; nf++) {
        int n = bn + wn + (nf << 3) + (t << 1);
        float2 bias = *(const float2*)(bb + n);
        int m0 = bm + wm + g, m1 = m0 + 8;
        float v0 = c[nf][0] + bias.x, v1 = c[nf][1] + bias.y;
        float v2 = c[nf][2] + bias.x, v3 = c[nf][3] + bias.y;
        if (z == 0) {
            v0 = 1.0f/(1.0f+expf(-v0)); v1 = 1.0f/(1.0f+expf(-v1));
            v2 = 1.0f/(1.0f+expf(-v2)); v3 = 1.0f/(1.0f+expf(-v3));
        }
        *(float2*)(o + (size_t)m0*CC + n) = make_float2(v0, v1);
        *(float2*)(o + (size_t)m1*CC + n) = make_float2(v2, v3);
    }
}

// ---------------- WKV (proven): 128 blocks x 1024 thr; writes wk (hi,lo) ----------------
__global__ void __launch_bounds__(1024, 1)
wkv_kernel(const float* __restrict__ wd) {
    __shared__ float s_acc[4][8][CC];
    const int tid = threadIdx.x;
    const int wid = tid >> 5, lane = tid & 31;
    const int seg = wid >> 3, rloc = wid & 7;
    const int row = (blockIdx.x << 3) + rloc;
    const int bb  = row >> 9;
    const int h = lane >> 4, p = lane & 15;
    const int c0 = p << 3;

    float bv8[8];
    {
        float4 k0 = *(const float4*)(g_k + (size_t)row*CC + c0);
        float4 k1 = *(const float4*)(g_k + (size_t)row*CC + c0 + 4);
        float4 w0 = *(const float4*)(wd + c0);
        float4 w1 = *(const float4*)(wd + c0 + 4);
        bv8[0] = k0.x * (-expf(w0.x)); bv8[1] = k0.y * (-expf(w0.y));
        bv8[2] = k0.z * (-expf(w0.z)); bv8[3] = k0.w * (-expf(w0.w));
        bv8[4] = k1.x * (-expf(w1.x)); bv8[5] = k1.y * (-expf(w1.y));
        bv8[6] = k1.z * (-expf(w1.z)); bv8[7] = k1.w * (-expf(w1.w));
    }
    float amax = bv8[0];
    #pragma unroll
    for (int i = 1; i < 8; i++) amax = fmaxf(amax, bv8[i]);
    #pragma unroll
    for (int o = 16; o; o >>= 1) amax = fmaxf(amax, __shfl_xor_sync(0xffffffffu, amax, o));
    #pragma unroll
    for (int i = 0; i < 8; i++) bv8[i] -= amax;

    const float inv511 = 1.0f/511.0f;
    const int l0 = seg << 7;
    const float s0 = (float)(511 - (l0 + h)) * inv511;
    ull E2[4], g2[4];
    #pragma unroll
    for (int j = 0; j < 4; j++) {
        E2[j] = pack2(expf(bv8[2*j]*s0),           expf(bv8[2*j+1]*s0));
        g2[j] = pack2(expf(-2.0f*bv8[2*j]*inv511), expf(-2.0f*bv8[2*j+1]*inv511));
    }
    ull acc2[4] = {0ull, 0ull, 0ull, 0ull};
    const float* vp = g_v + ((size_t)(bb << 9) + l0 + h)*CC + c0;

    #pragma unroll 4
    for (int i = 0; i < 64; i++) {
        ull tsum = add2(add2(E2[0], E2[1]), add2(E2[2], E2[3]));
        float zl, zh; unpack2(tsum, zl, zh);
        float z = zl + zh;
        #pragma unroll
        for (int o = 8; o; o >>= 1) z += __shfl_xor_sync(0xffffffffu, z, o);
        float inv = rcpa(z + 1e-6f);
        ull invd = pack2(inv, inv);
        ulonglong2 v01 = *(const ulonglong2*)(vp);
        ulonglong2 v23 = *(const ulonglong2*)(vp + 4);
        acc2[0] = fma2(mul2(E2[0], invd), v01.x, acc2[0]);
        acc2[1] = fma2(mul2(E2[1], invd), v01.y, acc2[1]);
        acc2[2] = fma2(mul2(E2[2], invd), v23.x, acc2[2]);
        acc2[3] = fma2(mul2(E2[3], invd), v23.y, acc2[3]);
        E2[0] = mul2(E2[0], g2[0]); E2[1] = mul2(E2[1], g2[1]);
        E2[2] = mul2(E2[2], g2[2]); E2[3] = mul2(E2[3], g2[3]);
        vp += 2*CC;
    }

    #pragma unroll
    for (int j = 0; j < 4; j++) {
        float x, y; unpack2(acc2[j], x, y);
        x += __shfl_xor_sync(0xffffffffu, x, 16);
        y += __shfl_xor_sync(0xffffffffu, y, 16);
        if (h == 0) {
            s_acc[seg][rloc][c0 + 2*j    ] = x;
            s_acc[seg][rloc][c0 + 2*j + 1] = y;
        }
    }
    __syncthreads();

    const int rl = tid >> 7, c = tid & (CC-1);
    float sum = (s_acc[0][rl][c] + s_acc[1][rl][c]) + (s_acc[2][rl][c] + s_acc[3][rl][c]);
    const int grow = (blockIdx.x << 3) + rl;
    float wkv = g_r[(size_t)grow*CC + c] * sum;
    g_wkhl[(size_t)grow*CC + c] = split2(wkv);
}

// ---------------- Wo GEMM + bias + residual -> y : grid (2, 32) ----------------
__global__ void __launch_bounds__(128)
wo_kernel(const float* __restrict__ bo, const float* __restrict__ x) {
    __shared__ SmemM S;
    const int bn = blockIdx.x << 6, bm = blockIdx.y << 5;
    float c[4][4];
    gemm_mma<CC>(S, g_wkhl, CC, bm, g_Whl + OFF_WO, CC, bn, c);
    const int lane = threadIdx.x & 31, w = threadIdx.x >> 5;
    const int g = lane >> 2, t = lane & 3;
    const int wm = (w >> 1) << 4, wn = (w & 1) << 5;
    #pragma unroll
    for (int nf = 0; nf < 4; nf++) {
        int n = bn + wn + (nf << 3) + (t << 1);
        float2 bias = *(const float2*)(bo + n);
        int m0 = bm + wm + g, m1 = m0 + 8;
        float2 x0 = *(const float2*)(x + (size_t)m0*CC + n);
        float2 x1 = *(const float2*)(x + (size_t)m1*CC + n);
        *(float2*)(g_y + (size_t)m0*CC + n) =
            make_float2(c[nf][0] + bias.x + x0.x, c[nf][1] + bias.y + x0.y);
        *(float2*)(g_y + (size_t)m1*CC + n) =
            make_float2(c[nf][2] + bias.x + x1.x, c[nf][3] + bias.y + x1.y);
    }
}

// ---------------- LN2: y -> h2 (hi,lo) : grid 128, 256 thr ----------------
__global__ void __launch_bounds__(256)
ln2_kernel(const float* __restrict__ gam, const float* __restrict__ bet) {
    const int tid = threadIdx.x, w = tid >> 5, lane = tid & 31;
    const int row = (blockIdx.x << 3) + w;
    float4 g4 = *(const float4*)(gam + (lane << 2));
    float4 b4 = *(const float4*)(bet + (lane << 2));
    float4 yv = *(const float4*)(g_y + (size_t)row*CC + (lane << 2));
    float mean = wsum((yv.x + yv.y) + (yv.z + yv.w)) * (1.0f/CC);
    float d0 = yv.x - mean, d1 = yv.y - mean, d2 = yv.z - mean, d3 = yv.w - mean;
    float rs = rsqrtf(wsum((d0*d0 + d1*d1) + (d2*d2 + d3*d3)) * (1.0f/CC) + 1e-5f);
    float2* o = g_h2hl + (size_t)row*CC + (lane << 2);
    o[0] = split2(d0*rs*g4.x + b4.x);
    o[1] = split2(d1*rs*g4.y + b4.y);
    o[2] = split2(d2*rs*g4.z + b4.z);
    o[3] = split2(d3*rs*g4.w + b4.w);
}

// ---------------- W1 GEMM + exact gelu -> mid (hi,lo) : grid (8, 32) ----------------
__global__ void __launch_bounds__(128)
w1_kernel(const float* __restrict__ b1) {
    __shared__ SmemM S;
    const int bn = blockIdx.x << 6, bm = blockIdx.y << 5;
    float c[4][4];
    gemm_mma<CC>(S, g_h2hl, CC, bm, g_Whl + OFF_W1, HH, bn, c);
    const int lane = threadIdx.x & 31, w = threadIdx.x >> 5;
    const int g = lane >> 2, t = lane & 3;
    const int wm = (w >> 1) << 4, wn = (w & 1) << 5;
    const float gc = 0.70710678118654752f;
    #pragma unroll
    for (int nf = 0; nf < 4; nf++) {
        int n = bn + wn + (nf << 3) + (t << 1);
        float2 bias = *(const float2*)(b1 + n);
        int m0 = bm + wm + g, m1 = m0 + 8;
        float v0 = c[nf][0] + bias.x, v1 = c[nf][1] + bias.y;
        float v2 = c[nf][2] + bias.x, v3 = c[nf][3] + bias.y;
        v0 = 0.5f*v0*(1.0f + erff(v0*gc));
        v1 = 0.5f*v1*(1.0f + erff(v1*gc));
        v2 = 0.5f*v2*(1.0f + erff(v2*gc));
        v3 = 0.5f*v3*(1.0f + erff(v3*gc));
        float2 s0 = split2(v0), s1 = split2(v1), s2 = split2(v2), s3 = split2(v3);
        *(float4*)&g_midhl[(size_t)m0*HH + n] = make_float4(s0.x, s0.y, s1.x, s1.y);
        *(float4*)&g_midhl[(size_t)m1*HH + n] = make_float4(s2.x, s2.y, s3.x, s3.y);
    }
}

// ---------------- W2 GEMM (K=512) + bias + residual -> out : grid (2, 32) ----------------
__global__ void __launch_bounds__(128)
w2_kernel(const float* __restrict__ b2, float* __restrict__ out) {
    __shared__ SmemM S;
    const int bn = blockIdx.x << 6, bm = blockIdx.y << 5;
    float c[4][4];
    gemm_mma<HH>(S, g_midhl, HH, bm, g_Whl + OFF_W2, CC, bn, c);
    const int lane = threadIdx.x & 31, w = threadIdx.x >> 5;
    const int g = lane >> 2, t = lane & 3;
    const int wm = (w >> 1) << 4, wn = (w & 1) << 5;
    #pragma unroll
    for (int nf = 0; nf < 4; nf++) {
        int n = bn + wn + (nf << 3) + (t << 1);
        float2 bias = *(const float2*)(b2 + n);
        int m0 = bm + wm + g, m1 = m0 + 8;
        float2 y0 = *(const float2*)(g_y + (size_t)m0*CC + n);
        float2 y1 = *(const float2*)(g_y + (size_t)m1*CC + n);
        *(float2*)(out + (size_t)m0*CC + n) =
            make_float2(c[nf][0] + bias.x + y0.x, c[nf][1] + bias.y + y0.y);
        *(float2*)(out + (size_t)m1*CC + n) =
            make_float2(c[nf][2] + bias.x + y1.x, c[nf][3] + bias.y + y1.y);
    }
}

// ---------------- launch ----------------
extern "C" void kernel_launch(void* const* d_in, const int* in_sizes, int n_in,
                              void* d_out, int out_size) {
    const float* x       = (const float*)d_in[0];
    const float* ln1_g   = (const float*)d_in[1];
    const float* ln1_b   = (const float*)d_in[2];
    const float* mu      = (const float*)d_in[3];
    const float* Wr      = (const float*)d_in[4];
    const float* br      = (const float*)d_in[5];
    const float* Wk      = (const float*)d_in[6];
    const float* bk      = (const float*)d_in[7];
    const float* Wv      = (const float*)d_in[8];
    const float* bv      = (const float*)d_in[9];
    const float* w_decay = (const float*)d_in[10];
    const float* Wo      = (const float*)d_in[11];
    const float* bo      = (const float*)d_in[12];
    const float* ln2_g   = (const float*)d_in[13];
    const float* ln2_b   = (const float*)d_in[14];
    const float* W1      = (const float*)d_in[15];
    const float* b1      = (const float*)d_in[16];
    const float* W2      = (const float*)d_in[17];
    const float* b2      = (const float*)d_in[18];
    float* out = (float*)d_out;

    prep_kernel<<<192, 256>>>(Wr, Wk, Wv, Wo, W1, W2);
    ln_shift_kernel<<<128, 256>>>(x, ln1_g, ln1_b, mu);
    rkv_kernel<<<dim3(2, 32, 3), 128>>>(br, bk, bv);
    wkv_kernel<<<128, 1024>>>(w_decay);
    wo_kernel<<<dim3(2, 32), 128>>>(bo, x);
    ln2_kernel<<<128, 256>>>(ln2_g, ln2_b);
    w1_kernel<<<dim3(8, 32), 128>>>(b1);
    w2_kernel<<<dim3(2, 32), 128>>>(b2, out);
}

// round 12
// speedup vs baseline: 1.0038x; 1.0038x over previous
#include <cuda_runtime.h>
#include <math.h>
#include <stdint.h>

#define TT 512
#define CC 128
#define HH 512
#define ROWS 1024

// ---------------- global scratch ----------------
__device__ __align__(16) float2 g_hshl [ROWS*CC];
__device__ float  g_r [ROWS*CC];
__device__ float  g_k [ROWS*CC];
__device__ float  g_v [ROWS*CC];
__device__ __align__(16) float2 g_wkhl [ROWS*CC];
__device__ float  g_y [ROWS*CC];
__device__ __align__(16) float2 g_h2hl [ROWS*CC];
__device__ __align__(16) float2 g_midhl[ROWS*HH];
// weights split hi/lo: [Wr | Wk | Wv | Wo | W1 | W2] (layout [K][N] each)
#define OFF_WR 0
#define OFF_WK 16384
#define OFF_WV 32768
#define OFF_WO 49152
#define OFF_W1 65536
#define OFF_W2 131072
__device__ __align__(16) float2 g_Whl[196608];

// ---------------- helpers ----------------
__device__ __forceinline__ float wsum(float x) {
    #pragma unroll
    for (int o = 16; o; o >>= 1) x += __shfl_xor_sync(0xffffffffu, x, o);
    return x;
}
__device__ __forceinline__ float rcpa(float x) {
    float r; asm("rcp.approx.f32 %0, %1;" : "=f"(r) : "f"(x)); return r;
}
typedef unsigned long long ull;
__device__ __forceinline__ ull pack2(float x, float y) {
    ull r; asm("mov.b64 %0, {%1, %2};" : "=l"(r) : "f"(x), "f"(y)); return r;
}
__device__ __forceinline__ void unpack2(ull p, float& x, float& y) {
    asm("mov.b64 {%0, %1}, %2;" : "=f"(x), "=f"(y) : "l"(p));
}
__device__ __forceinline__ ull fma2(ull a, ull b, ull c) {
    ull d; asm("fma.rn.f32x2 %0, %1, %2, %3;" : "=l"(d) : "l"(a), "l"(b), "l"(c)); return d;
}
__device__ __forceinline__ ull mul2(ull a, ull b) {
    ull d; asm("mul.rn.f32x2 %0, %1, %2;" : "=l"(d) : "l"(a), "l"(b)); return d;
}
__device__ __forceinline__ ull add2(ull a, ull b) {
    ull d; asm("add.rn.f32x2 %0, %1, %2;" : "=l"(d) : "l"(a), "l"(b)); return d;
}
__device__ __forceinline__ void cpasync16(uint32_t saddr, const void* g) {
    asm volatile("cp.async.ca.shared.global [%0], [%1], 16;" :: "r"(saddr), "l"(g));
}
__device__ __forceinline__ void cpcommit() { asm volatile("cp.async.commit_group;"); }
template<int N> __device__ __forceinline__ void cpwait() {
    asm volatile("cp.async.wait_group %0;" :: "n"(N));
}
__device__ __forceinline__ uint32_t s2u(const void* p) {
    return (uint32_t)__cvta_generic_to_shared(p);
}
// split x into (hi, lo) tf32 parts (3xTF32 scheme)
__device__ __forceinline__ float2 split2(float x) {
    uint32_t h; asm("cvt.rna.tf32.f32 %0, %1;" : "=r"(h) : "f"(x));
    float hf = __uint_as_float(h);
    float r = x - hf;
    uint32_t l; asm("cvt.rna.tf32.f32 %0, %1;" : "=r"(l) : "f"(r));
    return make_float2(hf, __uint_as_float(l));
}
__device__ __forceinline__ uint32_t fu(float x) { return __float_as_uint(x); }

__device__ __forceinline__ void mma_tf32(float (&c)[4], uint32_t a0, uint32_t a1,
                                         uint32_t a2, uint32_t a3,
                                         uint32_t b0, uint32_t b1) {
    asm volatile(
        "mma.sync.aligned.m16n8k8.row.col.f32.tf32.tf32.f32 "
        "{%0,%1,%2,%3}, {%4,%5,%6,%7}, {%8,%9}, {%0,%1,%2,%3};"
        : "+f"(c[0]), "+f"(c[1]), "+f"(c[2]), "+f"(c[3])
        : "r"(a0), "r"(a1), "r"(a2), "r"(a3), "r"(b0), "r"(b1));
}

// ---------------- prep: split all weights into (hi,lo) ----------------
__global__ void __launch_bounds__(256)
prep_kernel(const float* __restrict__ Wr, const float* __restrict__ Wk,
            const float* __restrict__ Wv, const float* __restrict__ Wo,
            const float* __restrict__ W1, const float* __restrict__ W2) {
    for (int i = blockIdx.x*256 + threadIdx.x; i < 196608; i += gridDim.x*256) {
        float x;
        if (i < 65536) {
            int m = i >> 14, off = i & 16383;
            const float* s = (m == 0) ? Wr : (m == 1) ? Wk : (m == 2) ? Wv : Wo;
            x = s[off];
        } else if (i < 131072) {
            x = W1[i - 65536];
        } else {
            x = W2[i - 131072];
        }
        g_Whl[i] = split2(x);
    }
}

// ---------------- fused LN1 + TemporalShift -> hs (hi,lo) ----------------
__global__ void __launch_bounds__(256)
ln_shift_kernel(const float* __restrict__ x,
                const float* __restrict__ gam, const float* __restrict__ bet,
                const float* __restrict__ mu) {
    __shared__ float sh[10][CC];
    const int tid = threadIdx.x;
    const int w = tid >> 5, lane = tid & 31;
    const int b  = blockIdx.x >> 6;
    const int t0 = (blockIdx.x & 63) << 3;

    float4 g4 = *(const float4*)(gam + (lane << 2));
    float4 b4 = *(const float4*)(bet + (lane << 2));

    for (int hr = w; hr < 10; hr += 8) {
        int t = t0 - 1 + hr;
        bool ok = (t >= 0) && (t < TT);
        float4 xv = make_float4(0.f, 0.f, 0.f, 0.f);
        if (ok) xv = *(const float4*)(x + (size_t)((b << 9) + t)*CC + (lane << 2));
        float mean = wsum((xv.x + xv.y) + (xv.z + xv.w)) * (1.0f/CC);
        float d0 = xv.x - mean, d1 = xv.y - mean, d2 = xv.z - mean, d3 = xv.w - mean;
        float rs = rsqrtf(wsum((d0*d0 + d1*d1) + (d2*d2 + d3*d3)) * (1.0f/CC) + 1e-5f);
        int c = lane << 2;
        sh[hr][c+0] = ok ? d0*rs*g4.x + b4.x : 0.f;
        sh[hr][c+1] = ok ? d1*rs*g4.y + b4.y : 0.f;
        sh[hr][c+2] = ok ? d2*rs*g4.z + b4.z : 0.f;
        sh[hr][c+3] = ok ? d3*rs*g4.w + b4.w : 0.f;
    }
    __syncthreads();
    for (int i = tid; i < 8*CC; i += 256) {
        int rl = i >> 7, c = i & (CC-1);
        float val = sh[rl+1][c];
        float shv = (c < CC/2) ? sh[rl][c] : sh[rl+2][c];
        float hsv = val + mu[c]*shv;
        g_hshl[(size_t)((b << 9) + t0 + rl)*CC + c] = split2(hsv);
    }
}

// ================= tensor-core GEMM: tile 32x64, 128 thr, 3xTF32 =================
struct __align__(16) SmemM {
    float2 A[2][32][20];   // [buf][tile row][k in chunk]  (pitch 20 -> conflict-free)
    float2 W[2][16][68];   // [buf][k in chunk][n in tile] (pitch 68 -> conflict-free)
};

template<int K>
__device__ __forceinline__ void gemm_mma(SmemM& S,
                                         const float2* __restrict__ Ahl, int lda, int bm,
                                         const float2* __restrict__ Whl, int ldw, int bn,
                                         float (&c)[4][4]) {
    const int tid = threadIdx.x, w = tid >> 5, lane = tid & 31;
    const int g = lane >> 2, t = lane & 3;
    const int wm = (w >> 1) << 4, wn = (w & 1) << 5;
    constexpr int NC = K / 16;

    auto stage = [&](int ck, int buf) {
        #pragma unroll
        for (int j = 0; j < 2; j++) {
            int idx = tid + j*128;
            int row = idx >> 3, q = idx & 7;
            cpasync16(s2u(&S.A[buf][row][q*2]),
                      Ahl + (size_t)(bm + row)*lda + ck*16 + q*2);
        }
        #pragma unroll
        for (int j = 0; j < 4; j++) {
            int idx = tid + j*128;
            int kr = idx >> 5, q = idx & 31;
            cpasync16(s2u(&S.W[buf][kr][q*2]),
                      Whl + (size_t)(ck*16 + kr)*ldw + bn + q*2);
        }
        cpcommit();
    };

    stage(0, 0);
    #pragma unroll
    for (int nf = 0; nf < 4; nf++)
        #pragma unroll
        for (int i = 0; i < 4; i++) c[nf][i] = 0.f;

    #pragma unroll 1
    for (int ck = 0; ck < NC; ck++) {
        if (ck + 1 < NC) { stage(ck + 1, (ck + 1) & 1); cpwait<1>(); }
        else             { cpwait<0>(); }
        __syncthreads();
        const int buf = ck & 1;
        #pragma unroll
        for (int k8 = 0; k8 < 2; k8++) {
            const int kb = k8 << 3;
            float2 a00 = S.A[buf][wm + g    ][kb + t];
            float2 a10 = S.A[buf][wm + g + 8][kb + t];
            float2 a01 = S.A[buf][wm + g    ][kb + t + 4];
            float2 a11 = S.A[buf][wm + g + 8][kb + t + 4];
            uint32_t ah0 = fu(a00.x), ah1 = fu(a10.x), ah2 = fu(a01.x), ah3 = fu(a11.x);
            uint32_t al0 = fu(a00.y), al1 = fu(a10.y), al2 = fu(a01.y), al3 = fu(a11.y);
            #pragma unroll
            for (int nf = 0; nf < 4; nf++) {
                float2 b0 = S.W[buf][kb + t    ][wn + (nf << 3) + g];
                float2 b1 = S.W[buf][kb + t + 4][wn + (nf << 3) + g];
                mma_tf32(c[nf], ah0, ah1, ah2, ah3, fu(b0.x), fu(b1.x));  // hi*hi
                mma_tf32(c[nf], ah0, ah1, ah2, ah3, fu(b0.y), fu(b1.y));  // hi*lo
                mma_tf32(c[nf], al0, al1, al2, al3, fu(b0.x), fu(b1.x));  // lo*hi
            }
        }
        __syncthreads();
    }
}

// ---------------- r/k/v GEMMs: grid (2, 32, 3), 128 thr ----------------
__global__ void __launch_bounds__(128)
rkv_kernel(const float* __restrict__ br, const float* __restrict__ bk,
           const float* __restrict__ bv) {
    __shared__ SmemM S;
    const int z = blockIdx.z;
    const float2* Wz = g_Whl + ((z == 0) ? OFF_WR : (z == 1) ? OFF_WK : OFF_WV);
    const float* bb  = (z == 0) ? br : (z == 1) ? bk : bv;
    float* o         = (z == 0) ? g_r : (z == 1) ? g_k : g_v;
    const int bn = blockIdx.x << 6, bm = blockIdx.y << 5;
    float c[4][4];
    gemm_mma<CC>(S, g_hshl, CC, bm, Wz, CC, bn, c);
    const int lane = threadIdx.x & 31, w = threadIdx.x >> 5;
    const int g = lane >> 2, t = lane & 3;
    const int wm = (w >> 1) << 4, wn = (w & 1) << 5;
    #pragma unroll
    for (int nf = 0; nf < 4; nf++) {
        int n = bn + wn + (nf << 3) + (t << 1);
        float2 bias = *(const float2*)(bb + n);
        int m0 = bm + wm + g, m1 = m0 + 8;
        float v0 = c[nf][0] + bias.x, v1 = c[nf][1] + bias.y;
        float v2 = c[nf][2] + bias.x, v3 = c[nf][3] + bias.y;
        if (z == 0) {
            v0 = 1.0f/(1.0f+expf(-v0)); v1 = 1.0f/(1.0f+expf(-v1));
            v2 = 1.0f/(1.0f+expf(-v2)); v3 = 1.0f/(1.0f+expf(-v3));
        }
        *(float2*)(o + (size_t)m0*CC + n) = make_float2(v0, v1);
        *(float2*)(o + (size_t)m1*CC + n) = make_float2(v2, v3);
    }
}

// ======== WKV v2: warp owns 4 rows sharing one v stream (4x fewer LDG wavefronts) ====
// Block = 256 thr = 8 warps = 2 row-quads x 4 segs; grid 128 (8 rows/block).
// Lane: h = lane>>4 (even/odd l), p = lane&15 -> 8 channels c0 = 8p.
// x_b == x_f identity -> wk = r * x_f; output written pre-split (hi,lo).
__global__ void __launch_bounds__(256, 1)
wkv_kernel(const float* __restrict__ wd) {
    __shared__ float s_acc[4][8][CC];
    const int tid = threadIdx.x;
    const int wid = tid >> 5, lane = tid & 31;
    const int seg = wid & 3, quad = wid >> 2;          // seg 0..3, quad 0..1
    const int rbase = (blockIdx.x << 3) + (quad << 2); // first of 4 rows
    const int bb  = rbase >> 9;
    const int h = lane >> 4, p = lane & 15;
    const int c0 = p << 3;

    const float inv511 = 1.0f/511.0f;
    const int l0 = seg << 7;
    const float s0 = (float)(511 - (l0 + h)) * inv511;

    float4 w0 = *(const float4*)(wd + c0);
    float4 w1 = *(const float4*)(wd + c0 + 4);
    float nw[8];
    nw[0] = -expf(w0.x); nw[1] = -expf(w0.y); nw[2] = -expf(w0.z); nw[3] = -expf(w0.w);
    nw[4] = -expf(w1.x); nw[5] = -expf(w1.y); nw[6] = -expf(w1.z); nw[7] = -expf(w1.w);

    ull E[4][4], G[4][4], acc[4][4];
    #pragma unroll
    for (int r = 0; r < 4; r++) {
        float bv8[8];
        float4 k0 = *(const float4*)(g_k + (size_t)(rbase + r)*CC + c0);
        float4 k1 = *(const float4*)(g_k + (size_t)(rbase + r)*CC + c0 + 4);
        bv8[0] = k0.x*nw[0]; bv8[1] = k0.y*nw[1]; bv8[2] = k0.z*nw[2]; bv8[3] = k0.w*nw[3];
        bv8[4] = k1.x*nw[4]; bv8[5] = k1.y*nw[5]; bv8[6] = k1.z*nw[6]; bv8[7] = k1.w*nw[7];
        float amax = bv8[0];
        #pragma unroll
        for (int i = 1; i < 8; i++) amax = fmaxf(amax, bv8[i]);
        #pragma unroll
        for (int o = 16; o; o >>= 1) amax = fmaxf(amax, __shfl_xor_sync(0xffffffffu, amax, o));
        #pragma unroll
        for (int i = 0; i < 8; i++) bv8[i] -= amax;
        #pragma unroll
        for (int j = 0; j < 4; j++) {
            E[r][j]   = pack2(expf(bv8[2*j]*s0),           expf(bv8[2*j+1]*s0));
            G[r][j]   = pack2(expf(-2.0f*bv8[2*j]*inv511), expf(-2.0f*bv8[2*j+1]*inv511));
            acc[r][j] = 0ull;
        }
    }

    const float* vp = g_v + ((size_t)(bb << 9) + l0 + h)*CC + c0;

    #pragma unroll 2
    for (int i = 0; i < 64; i++) {
        ulonglong2 v01 = *(const ulonglong2*)(vp);
        ulonglong2 v23 = *(const ulonglong2*)(vp + 4);
        #pragma unroll
        for (int r = 0; r < 4; r++) {
            ull tsum = add2(add2(E[r][0], E[r][1]), add2(E[r][2], E[r][3]));
            float zl, zh; unpack2(tsum, zl, zh);
            float z = zl + zh;
            #pragma unroll
            for (int o = 8; o; o >>= 1) z += __shfl_xor_sync(0xffffffffu, z, o);
            float inv = rcpa(z + 1e-6f);
            ull invd = pack2(inv, inv);
            acc[r][0] = fma2(mul2(E[r][0], invd), v01.x, acc[r][0]);
            acc[r][1] = fma2(mul2(E[r][1], invd), v01.y, acc[r][1]);
            acc[r][2] = fma2(mul2(E[r][2], invd), v23.x, acc[r][2]);
            acc[r][3] = fma2(mul2(E[r][3], invd), v23.y, acc[r][3]);
            E[r][0] = mul2(E[r][0], G[r][0]); E[r][1] = mul2(E[r][1], G[r][1]);
            E[r][2] = mul2(E[r][2], G[r][2]); E[r][3] = mul2(E[r][3], G[r][3]);
        }
        vp += 2*CC;
    }

    // combine even/odd halves, write per-seg partials
    #pragma unroll
    for (int r = 0; r < 4; r++) {
        #pragma unroll
        for (int j = 0; j < 4; j++) {
            float x, y; unpack2(acc[r][j], x, y);
            x += __shfl_xor_sync(0xffffffffu, x, 16);
            y += __shfl_xor_sync(0xffffffffu, y, 16);
            if (h == 0) {
                s_acc[seg][(quad << 2) + r][c0 + 2*j    ] = x;
                s_acc[seg][(quad << 2) + r][c0 + 2*j + 1] = y;
            }
        }
    }
    __syncthreads();

    // finalize: 8 rows x 128 c, 4 values per thread
    for (int idx = tid; idx < 8*CC; idx += 256) {
        int rl = idx >> 7, c = idx & (CC-1);
        float sum = (s_acc[0][rl][c] + s_acc[1][rl][c]) + (s_acc[2][rl][c] + s_acc[3][rl][c]);
        int grow = (blockIdx.x << 3) + rl;
        float wkv = g_r[(size_t)grow*CC + c] * sum;
        g_wkhl[(size_t)grow*CC + c] = split2(wkv);
    }
}

// ---------------- Wo GEMM + bias + residual -> y : grid (2, 32) ----------------
__global__ void __launch_bounds__(128)
wo_kernel(const float* __restrict__ bo, const float* __restrict__ x) {
    __shared__ SmemM S;
    const int bn = blockIdx.x << 6, bm = blockIdx.y << 5;
    float c[4][4];
    gemm_mma<CC>(S, g_wkhl, CC, bm, g_Whl + OFF_WO, CC, bn, c);
    const int lane = threadIdx.x & 31, w = threadIdx.x >> 5;
    const int g = lane >> 2, t = lane & 3;
    const int wm = (w >> 1) << 4, wn = (w & 1) << 5;
    #pragma unroll
    for (int nf = 0; nf < 4; nf++) {
        int n = bn + wn + (nf << 3) + (t << 1);
        float2 bias = *(const float2*)(bo + n);
        int m0 = bm + wm + g, m1 = m0 + 8;
        float2 x0 = *(const float2*)(x + (size_t)m0*CC + n);
        float2 x1 = *(const float2*)(x + (size_t)m1*CC + n);
        *(float2*)(g_y + (size_t)m0*CC + n) =
            make_float2(c[nf][0] + bias.x + x0.x, c[nf][1] + bias.y + x0.y);
        *(float2*)(g_y + (size_t)m1*CC + n) =
            make_float2(c[nf][2] + bias.x + x1.x, c[nf][3] + bias.y + x1.y);
    }
}

// ---------------- LN2: y -> h2 (hi,lo) : grid 128, 256 thr ----------------
__global__ void __launch_bounds__(256)
ln2_kernel(const float* __restrict__ gam, const float* __restrict__ bet) {
    const int tid = threadIdx.x, w = tid >> 5, lane = tid & 31;
    const int row = (blockIdx.x << 3) + w;
    float4 g4 = *(const float4*)(gam + (lane << 2));
    float4 b4 = *(const float4*)(bet + (lane << 2));
    float4 yv = *(const float4*)(g_y + (size_t)row*CC + (lane << 2));
    float mean = wsum((yv.x + yv.y) + (yv.z + yv.w)) * (1.0f/CC);
    float d0 = yv.x - mean, d1 = yv.y - mean, d2 = yv.z - mean, d3 = yv.w - mean;
    float rs = rsqrtf(wsum((d0*d0 + d1*d1) + (d2*d2 + d3*d3)) * (1.0f/CC) + 1e-5f);
    float2* o = g_h2hl + (size_t)row*CC + (lane << 2);
    o[0] = split2(d0*rs*g4.x + b4.x);
    o[1] = split2(d1*rs*g4.y + b4.y);
    o[2] = split2(d2*rs*g4.z + b4.z);
    o[3] = split2(d3*rs*g4.w + b4.w);
}

// ---------------- W1 GEMM + exact gelu -> mid (hi,lo) : grid (8, 32) ----------------
__global__ void __launch_bounds__(128)
w1_kernel(const float* __restrict__ b1) {
    __shared__ SmemM S;
    const int bn = blockIdx.x << 6, bm = blockIdx.y << 5;
    float c[4][4];
    gemm_mma<CC>(S, g_h2hl, CC, bm, g_Whl + OFF_W1, HH, bn, c);
    const int lane = threadIdx.x & 31, w = threadIdx.x >> 5;
    const int g = lane >> 2, t = lane & 3;
    const int wm = (w >> 1) << 4, wn = (w & 1) << 5;
    const float gc = 0.70710678118654752f;
    #pragma unroll
    for (int nf = 0; nf < 4; nf++) {
        int n = bn + wn + (nf << 3) + (t << 1);
        float2 bias = *(const float2*)(b1 + n);
        int m0 = bm + wm + g, m1 = m0 + 8;
        float v0 = c[nf][0] + bias.x, v1 = c[nf][1] + bias.y;
        float v2 = c[nf][2] + bias.x, v3 = c[nf][3] + bias.y;
        v0 = 0.5f*v0*(1.0f + erff(v0*gc));
        v1 = 0.5f*v1*(1.0f + erff(v1*gc));
        v2 = 0.5f*v2*(1.0f + erff(v2*gc));
        v3 = 0.5f*v3*(1.0f + erff(v3*gc));
        float2 s0 = split2(v0), s1 = split2(v1), s2 = split2(v2), s3 = split2(v3);
        *(float4*)&g_midhl[(size_t)m0*HH + n] = make_float4(s0.x, s0.y, s1.x, s1.y);
        *(float4*)&g_midhl[(size_t)m1*HH + n] = make_float4(s2.x, s2.y, s3.x, s3.y);
    }
}

// ---------------- W2 GEMM (K=512) + bias + residual -> out : grid (2, 32) ----------------
__global__ void __launch_bounds__(128)
w2_kernel(const float* __restrict__ b2, float* __restrict__ out) {
    __shared__ SmemM S;
    const int bn = blockIdx.x << 6, bm = blockIdx.y << 5;
    float c[4][4];
    gemm_mma<HH>(S, g_midhl, HH, bm, g_Whl + OFF_W2, CC, bn, c);
    const int lane = threadIdx.x & 31, w = threadIdx.x >> 5;
    const int g = lane >> 2, t = lane & 3;
    const int wm = (w >> 1) << 4, wn = (w & 1) << 5;
    #pragma unroll
    for (int nf = 0; nf < 4; nf++) {
        int n = bn + wn + (nf << 3) + (t << 1);
        float2 bias = *(const float2*)(b2 + n);
        int m0 = bm + wm + g, m1 = m0 + 8;
        float2 y0 = *(const float2*)(g_y + (size_t)m0*CC + n);
        float2 y1 = *(const float2*)(g_y + (size_t)m1*CC + n);
        *(float2*)(out + (size_t)m0*CC + n) =
            make_float2(c[nf][0] + bias.x + y0.x, c[nf][1] + bias.y + y0.y);
        *(float2*)(out + (size_t)m1*CC + n) =
            make_float2(c[nf][2] + bias.x + y1.x, c[nf][3] + bias.y + y1.y);
    }
}

// ---------------- launch ----------------
extern "C" void kernel_launch(void* const* d_in, const int* in_sizes, int n_in,
                              void* d_out, int out_size) {
    const float* x       = (const float*)d_in[0];
    const float* ln1_g   = (const float*)d_in[1];
    const float* ln1_b   = (const float*)d_in[2];
    const float* mu      = (const float*)d_in[3];
    const float* Wr      = (const float*)d_in[4];
    const float* br      = (const float*)d_in[5];
    const float* Wk      = (const float*)d_in[6];
    const float* bk      = (const float*)d_in[7];
    const float* Wv      = (const float*)d_in[8];
    const float* bv      = (const float*)d_in[9];
    const float* w_decay = (const float*)d_in[10];
    const float* Wo      = (const float*)d_in[11];
    const float* bo      = (const float*)d_in[12];
    const float* ln2_g   = (const float*)d_in[13];
    const float* ln2_b   = (const float*)d_in[14];
    const float* W1      = (const float*)d_in[15];
    const float* b1      = (const float*)d_in[16];
    const float* W2      = (const float*)d_in[17];
    const float* b2      = (const float*)d_in[18];
    float* out = (float*)d_out;

    prep_kernel<<<192, 256>>>(Wr, Wk, Wv, Wo, W1, W2);
    ln_shift_kernel<<<128, 256>>>(x, ln1_g, ln1_b, mu);
    rkv_kernel<<<dim3(2, 32, 3), 128>>>(br, bk, bv);
    wkv_kernel<<<128, 256>>>(w_decay);
    wo_kernel<<<dim3(2, 32), 128>>>(bo, x);
    ln2_kernel<<<128, 256>>>(ln2_g, ln2_b);
    w1_kernel<<<dim3(8, 32), 128>>>(b1);
    w2_kernel<<<dim3(2, 32), 128>>>(b2, out);
}